// round 2
// baseline (speedup 1.0000x reference)
#include <cuda_runtime.h>
#include <math.h>

#define N_NODES 4096
#define NFEAT   128
#define NHID    128
#define NHEADS  4
#define NCLASS  32
#define KEDGE   32
#define ALPHA_LRELU 0.2f

// ---------------- scratch (no allocations allowed) ----------------
__device__ float g_h  [N_NODES * NHEADS * NHID];   // [n][head*128+d]
__device__ float g_xc [N_NODES * NHEADS * NHID];   // [n][head*128+d]
__device__ float g_f1 [NHEADS * N_NODES];
__device__ float g_f2 [NHEADS * N_NODES];
__device__ float g_w  [N_NODES * NHEADS * KEDGE];  // softmax weights, 0-padded
__device__ float g_h2 [N_NODES * NCLASS];
__device__ float g_f1o[N_NODES];
__device__ float g_f2o[N_NODES];
__device__ int   g_cnt[N_NODES];
__device__ int   g_nbr[N_NODES * KEDGE];

// ---------------- K1: dedup neighbor lists ----------------
__global__ void k_nbrs(const int* __restrict__ edge) {
    int row  = blockIdx.x * 4 + (threadIdx.x >> 5);
    int lane = threadIdx.x & 31;
    int e = edge[row * KEDGE + lane];
    bool valid = (e >= 0);
    unsigned key = valid ? (unsigned)e : (0x40000000u + (unsigned)lane);
    unsigned grp = __match_any_sync(0xffffffffu, key);
    bool uniq = valid && ((__ffs(grp) - 1) == lane);
    unsigned bal = __ballot_sync(0xffffffffu, uniq);
    if (uniq) {
        int pos = __popc(bal & ((1u << lane) - 1u));
        g_nbr[row * KEDGE + pos] = e;   // local index within 1024-block
    }
    if (lane == 0) g_cnt[row] = __popc(bal);
}

// ---------------- K2: h = x @ concat(Ws) ----------------
__global__ void k_gemm1(const float* __restrict__ X, const float* __restrict__ Ws) {
    __shared__ __align__(16) float As[64][68];  // [k][m], stride 68 keeps float4 align
    __shared__ __align__(16) float Bs[64][68];  // [k][n]
    int bx = blockIdx.x;          // 0..7  (64-col tiles of 512)
    int by = blockIdx.y;          // 0..63 (64-row tiles of 4096)
    int n0 = bx * 64;
    int head = n0 >> 7;
    int nloc = n0 & 127;
    const float* B = Ws + head * NFEAT * NHID;
    int m0 = by * 64;
    int tid = threadIdx.x;
    int tx = tid & 15, ty = tid >> 4;

    float acc[4][4] = {};
    for (int kc = 0; kc < NFEAT; kc += 64) {
        #pragma unroll
        for (int t = 0; t < 16; t++) {
            int e = t * 256 + tid;
            { int k = e & 63, m = e >> 6;
              As[k][m] = X[(m0 + m) * NFEAT + kc + k]; }
            { int n = e & 63, k = e >> 6;
              Bs[k][n] = B[(kc + k) * NHID + nloc + n]; }
        }
        __syncthreads();
        #pragma unroll 16
        for (int kk = 0; kk < 64; kk++) {
            float4 av = *(const float4*)&As[kk][ty * 4];
            float4 bv = *(const float4*)&Bs[kk][tx * 4];
            float a4[4] = {av.x, av.y, av.z, av.w};
            float b4[4] = {bv.x, bv.y, bv.z, bv.w};
            #pragma unroll
            for (int i = 0; i < 4; i++)
                #pragma unroll
                for (int j = 0; j < 4; j++)
                    acc[i][j] += a4[i] * b4[j];
        }
        __syncthreads();
    }
    #pragma unroll
    for (int i = 0; i < 4; i++) {
        float4 v = make_float4(acc[i][0], acc[i][1], acc[i][2], acc[i][3]);
        *(float4*)&g_h[(m0 + ty * 4 + i) * 512 + n0 + tx * 4] = v;
    }
}

// ---------------- K3: f1/f2 per (row, head) ----------------
__global__ void k_f12(const float* __restrict__ a) {
    int w    = blockIdx.x * 4 + (threadIdx.x >> 5);
    int row  = w >> 2;
    int head = w & 3;
    int lane = threadIdx.x & 31;
    const float* hp = g_h + row * 512 + head * 128;
    const float* ap = a + head * 256;
    float s1 = 0.f, s2 = 0.f;
    #pragma unroll
    for (int c = 0; c < 4; c++) {
        float hv = hp[lane + 32 * c];
        s1 += hv * ap[lane + 32 * c];
        s2 += hv * ap[128 + lane + 32 * c];
    }
    #pragma unroll
    for (int o = 16; o; o >>= 1) {
        s1 += __shfl_xor_sync(0xffffffffu, s1, o);
        s2 += __shfl_xor_sync(0xffffffffu, s2, o);
    }
    if (lane == 0) {
        g_f1[head * N_NODES + row] = s1;
        g_f2[head * N_NODES + row] = s2;
    }
}

// ---------------- K3b: softmax weights per (row, head), zero-padded ----------------
__global__ void k_wgt() {
    int tid  = threadIdx.x;                 // 512
    int row  = blockIdx.x * 4 + (tid >> 7);
    int head = (tid >> 5) & 3;
    int lane = tid & 31;
    int base = row & ~1023;
    int cnt  = g_cnt[row];
    int j    = g_nbr[row * KEDGE + lane];

    float e = -INFINITY;
    if (lane < cnt) {
        float t = g_f1[head * N_NODES + row] + g_f2[head * N_NODES + base + j];
        e = (t > 0.f) ? t : ALPHA_LRELU * t;
    }
    float m = e;
    #pragma unroll
    for (int o = 16; o; o >>= 1) m = fmaxf(m, __shfl_xor_sync(0xffffffffu, m, o));
    float p = (lane < cnt) ? __expf(e - m) : 0.f;
    float s = p;
    #pragma unroll
    for (int o = 16; o; o >>= 1) s += __shfl_xor_sync(0xffffffffu, s, o);
    g_w[(row * 4 + head) * KEDGE + lane] = p / s;   // 0 for padding lanes
}

// ---------------- K4: layer-1 aggregation via smem-staged tile ----------------
// grid: (dchunk=4, head=4, part*2+half=8), block 512, dyn smem 128KB
__global__ void k_attn1_agg() {
    extern __shared__ __align__(16) float tile[];   // [1024 nbrs][32 d]
    int dc   = blockIdx.x;
    int head = blockIdx.y;
    int part = blockIdx.z >> 1;
    int half = blockIdx.z & 1;
    int base = part << 10;
    int tid  = threadIdx.x;

    const float* src = g_h + (size_t)base * 512 + head * 128 + dc * 32;
    // stage tile: 1024x32 floats, float4-coalesced
    for (int i = tid; i < 1024 * 8; i += 512) {
        int j = i >> 3, d4 = i & 7;
        *(float4*)&tile[j * 32 + d4 * 4] = *(const float4*)&src[(size_t)j * 512 + d4 * 4];
    }
    __syncthreads();

    int lane = tid & 31, warp = tid >> 5;
    int row0 = base + half * 512 + warp * 32;
    const float* tl = tile + lane;
    #pragma unroll 1
    for (int r = 0; r < 32; r++) {
        int row = row0 + r;
        int off = g_nbr[row * KEDGE + lane] * 32;
        float w = g_w[(row * 4 + head) * KEDGE + lane];
        float acc0 = 0.f, acc1 = 0.f;
        #pragma unroll
        for (int k = 0; k < 32; k += 2) {
            float w0 = __shfl_sync(0xffffffffu, w, k);
            int   o0 = __shfl_sync(0xffffffffu, off, k);
            float w1 = __shfl_sync(0xffffffffu, w, k + 1);
            int   o1 = __shfl_sync(0xffffffffu, off, k + 1);
            acc0 += w0 * tl[o0];
            acc1 += w1 * tl[o1];
        }
        float acc = acc0 + acc1;
        float o = acc > 0.f ? acc : expm1f(acc);
        g_xc[(size_t)row * 512 + head * 128 + dc * 32 + lane] = o;
    }
}

// ---------------- K5: h2 = xc @ W_out, fused f1o/f2o ----------------
__global__ void k_gemm2(const float* __restrict__ W, const float* __restrict__ a_out) {
    __shared__ float Xs[32][132];
    __shared__ float Wsm[128][33];
    int r0 = blockIdx.x * 32;
    int tid = threadIdx.x;
    int lane = tid & 31, wid = tid >> 5;

    float acc[4] = {0.f, 0.f, 0.f, 0.f};
    for (int kc = 0; kc < 512; kc += 128) {
        #pragma unroll
        for (int t = 0; t < 16; t++) {
            int e = t * 256 + tid;
            { int r = e >> 7, k = e & 127;
              Xs[r][k] = g_xc[(r0 + r) * 512 + kc + k]; }
            { int k = e >> 5, n = e & 31;
              Wsm[k][n] = W[(kc + k) * 32 + n]; }
        }
        __syncthreads();
        #pragma unroll 8
        for (int kk = 0; kk < 128; kk++) {
            float w = Wsm[kk][lane];
            #pragma unroll
            for (int r = 0; r < 4; r++) acc[r] += Xs[wid * 4 + r][kk] * w;
        }
        __syncthreads();
    }
    float a1 = a_out[lane];
    float a2 = a_out[32 + lane];
    #pragma unroll
    for (int r = 0; r < 4; r++) {
        int row = r0 + wid * 4 + r;
        g_h2[row * 32 + lane] = acc[r];
        float s1 = acc[r] * a1;
        float s2 = acc[r] * a2;
        #pragma unroll
        for (int o = 16; o; o >>= 1) {
            s1 += __shfl_xor_sync(0xffffffffu, s1, o);
            s2 += __shfl_xor_sync(0xffffffffu, s2, o);
        }
        if (lane == 0) { g_f1o[row] = s1; g_f2o[row] = s2; }
    }
}

// ---------------- K6: layer-2 attention + elu + log_softmax ----------------
__global__ void k_attn2(float* __restrict__ out) {
    int row  = blockIdx.x * 4 + (threadIdx.x >> 5);
    int lane = threadIdx.x & 31;
    int base = row & ~1023;
    int cnt  = g_cnt[row];

    int j = 0;
    float e = -INFINITY;
    if (lane < cnt) {
        j = g_nbr[row * KEDGE + lane];
        float t = g_f1o[row] + g_f2o[base + j];
        e = (t > 0.f) ? t : ALPHA_LRELU * t;
    }
    float m = e;
    #pragma unroll
    for (int o = 16; o; o >>= 1) m = fmaxf(m, __shfl_xor_sync(0xffffffffu, m, o));
    float p = (lane < cnt) ? __expf(e - m) : 0.f;
    float s = p;
    #pragma unroll
    for (int o = 16; o; o >>= 1) s += __shfl_xor_sync(0xffffffffu, s, o);
    float wgt = p / s;

    float acc = 0.f;
    for (int k = 0; k < cnt; k++) {
        float wk = __shfl_sync(0xffffffffu, wgt, k);
        int   jk = __shfl_sync(0xffffffffu, j, k);
        acc += wk * g_h2[(base + jk) * 32 + lane];
    }
    float v = acc > 0.f ? acc : expm1f(acc);
    float m2 = v;
    #pragma unroll
    for (int o = 16; o; o >>= 1) m2 = fmaxf(m2, __shfl_xor_sync(0xffffffffu, m2, o));
    float se = __expf(v - m2);
    #pragma unroll
    for (int o = 16; o; o >>= 1) se += __shfl_xor_sync(0xffffffffu, se, o);
    out[row * 32 + lane] = v - m2 - logf(se);
}

// ---------------- launch ----------------
extern "C" void kernel_launch(void* const* d_in, const int* in_sizes, int n_in,
                              void* d_out, int out_size) {
    const float* x     = (const float*)d_in[0];
    const int*   edge  = (const int*)d_in[1];
    const float* Ws    = (const float*)d_in[3];
    const float* a     = (const float*)d_in[4];
    const float* W_out = (const float*)d_in[5];
    const float* a_out = (const float*)d_in[6];
    float* out = (float*)d_out;

    static bool attr_set = false;
    if (!attr_set) {
        cudaFuncSetAttribute(k_attn1_agg, cudaFuncAttributeMaxDynamicSharedMemorySize,
                             1024 * 32 * sizeof(float));
        attr_set = true;
    }

    k_nbrs<<<N_NODES / 4, 128>>>(edge);
    dim3 g1(8, 64);
    k_gemm1<<<g1, 256>>>(x, Ws);
    k_f12<<<N_NODES, 128>>>(a);
    k_wgt<<<N_NODES / 4, 512>>>();
    dim3 ga(4, 4, 8);
    k_attn1_agg<<<ga, 512, 1024 * 32 * sizeof(float)>>>();
    k_gemm2<<<N_NODES / 32, 256>>>(W_out, a_out);
    k_attn2<<<N_NODES / 4, 128>>>(out);
}

// round 3
// speedup vs baseline: 1.1025x; 1.1025x over previous
#include <cuda_runtime.h>
#include <math.h>

#define N_NODES 4096
#define NFEAT   128
#define NHID    128
#define NHEADS  4
#define NCLASS  32
#define KEDGE   32
#define ALPHA_LRELU 0.2f

// ---------------- scratch ----------------
__device__ float g_h  [N_NODES * NHEADS * NHID];   // [n][head*128+d]
__device__ float g_xc [N_NODES * NHEADS * NHID];
__device__ float g_f1 [NHEADS * N_NODES];
__device__ float g_f2 [NHEADS * N_NODES];
__device__ int2  g_wj [N_NODES * NHEADS * KEDGE];  // {w_bits, j*32}, w=0 padded
__device__ float g_h2 [N_NODES * NCLASS];
__device__ float g_f1o[N_NODES];
__device__ float g_f2o[N_NODES];

// ---------------- K1: h = x @ Ws  (128x128x16 SGEMM, fused f1/f2) ----------------
// grid (head=4, rowtile=32), block 256
__global__ void k_gemm1(const float* __restrict__ X, const float* __restrict__ Ws,
                        const float* __restrict__ a) {
    __shared__ __align__(16) float As[128][20];   // [m][k], pad 20
    __shared__ __align__(16) float Bs[16][128];   // [k][n]
    int head = blockIdx.x;
    int m0   = blockIdx.y * 128;
    const float* B = Ws + head * NFEAT * NHID;
    int tid = threadIdx.x;
    int tx = tid & 15, ty = tid >> 4;

    int ar  = tid >> 2, ac4 = (tid & 3) * 4;
    int bk  = tid >> 5, bn4 = (tid & 31) * 4;

    float acc[8][8] = {};
    for (int kc = 0; kc < NFEAT; kc += 16) {
        *(float4*)&As[ar][ac4]      = *(const float4*)&X[(m0 + ar) * NFEAT + kc + ac4];
        *(float4*)&As[64 + ar][ac4] = *(const float4*)&X[(m0 + 64 + ar) * NFEAT + kc + ac4];
        *(float4*)&Bs[bk][bn4]      = *(const float4*)&B[(kc + bk) * NHID + bn4];
        *(float4*)&Bs[8 + bk][bn4]  = *(const float4*)&B[(kc + 8 + bk) * NHID + bn4];
        __syncthreads();
        #pragma unroll
        for (int kk = 0; kk < 16; kk++) {
            float av[8], bv[8];
            #pragma unroll
            for (int i = 0; i < 4; i++) {
                av[i]     = As[ty * 4 + i][kk];
                av[4 + i] = As[64 + ty * 4 + i][kk];
            }
            float4 b0 = *(float4*)&Bs[kk][tx * 4];
            float4 b1 = *(float4*)&Bs[kk][64 + tx * 4];
            bv[0]=b0.x; bv[1]=b0.y; bv[2]=b0.z; bv[3]=b0.w;
            bv[4]=b1.x; bv[5]=b1.y; bv[6]=b1.z; bv[7]=b1.w;
            #pragma unroll
            for (int i = 0; i < 8; i++)
                #pragma unroll
                for (int j = 0; j < 8; j++)
                    acc[i][j] += av[i] * bv[j];
        }
        __syncthreads();
    }
    // store h
    #pragma unroll
    for (int i = 0; i < 8; i++) {
        int row = m0 + ((i < 4) ? (ty * 4 + i) : (64 + ty * 4 + i - 4));
        float* dst = &g_h[(size_t)row * 512 + head * 128];
        *(float4*)&dst[tx * 4]      = make_float4(acc[i][0], acc[i][1], acc[i][2], acc[i][3]);
        *(float4*)&dst[64 + tx * 4] = make_float4(acc[i][4], acc[i][5], acc[i][6], acc[i][7]);
    }
    // fused f1/f2: dot(h_row, a[:128]) and dot(h_row, a[128:])
    float a1j[8], a2j[8];
    #pragma unroll
    for (int j = 0; j < 8; j++) {
        int col = (j < 4) ? (tx * 4 + j) : (64 + tx * 4 + j - 4);
        a1j[j] = a[head * 256 + col];
        a2j[j] = a[head * 256 + 128 + col];
    }
    #pragma unroll
    for (int i = 0; i < 8; i++) {
        float s1 = 0.f, s2 = 0.f;
        #pragma unroll
        for (int j = 0; j < 8; j++) { s1 += acc[i][j] * a1j[j]; s2 += acc[i][j] * a2j[j]; }
        #pragma unroll
        for (int o = 8; o; o >>= 1) {
            s1 += __shfl_xor_sync(0xffffffffu, s1, o);
            s2 += __shfl_xor_sync(0xffffffffu, s2, o);
        }
        if (tx == 0) {
            int row = m0 + ((i < 4) ? (ty * 4 + i) : (64 + ty * 4 + i - 4));
            g_f1[head * N_NODES + row] = s1;
            g_f2[head * N_NODES + row] = s2;
        }
    }
}

// ---------------- K2: softmax weights, inline dedup, packed {w, j*32} ----------------
// grid 1024, block 512: 4 rows x 4 heads
__global__ void k_wgt(const int* __restrict__ edge) {
    int tid  = threadIdx.x;
    int row  = blockIdx.x * 4 + (tid >> 7);
    int head = (tid >> 5) & 3;
    int lane = tid & 31;
    int base = row & ~1023;

    int e = edge[row * KEDGE + lane];
    bool valid = (e >= 0);
    unsigned key = valid ? (unsigned)e : (0x40000000u + (unsigned)lane);
    unsigned grp = __match_any_sync(0xffffffffu, key);
    bool uniq = valid && ((__ffs(grp) - 1) == lane);

    float p = 0.f;
    if (uniq) {
        float t = g_f1[head * N_NODES + row] + g_f2[head * N_NODES + base + e];
        float la = (t > 0.f) ? t : ALPHA_LRELU * t;   // bounded: exp safe w/o max-sub
        p = __expf(la);
    }
    float s = p;
    #pragma unroll
    for (int o = 16; o; o >>= 1) s += __shfl_xor_sync(0xffffffffu, s, o);
    int2 v;
    v.x = __float_as_int(p / s);
    v.y = (valid ? e : 0) * 32;
    g_wj[(row * 4 + head) * KEDGE + lane] = v;
}

// ---------------- K3: layer-1 aggregation, smem tile + uniform wj loads ----------------
// grid (dchunk=4, head=4, part*2+half=8), block 1024, dyn smem 128KB
__global__ void k_attn1_agg() {
    extern __shared__ __align__(16) float tile[];   // [1024 nbrs][32 d]
    int dc   = blockIdx.x;
    int head = blockIdx.y;
    int part = blockIdx.z >> 1;
    int half = blockIdx.z & 1;
    int base = part << 10;
    int tid  = threadIdx.x;

    const float* src = g_h + (size_t)base * 512 + head * 128 + dc * 32;
    #pragma unroll
    for (int i = tid; i < 1024 * 8; i += 1024) {
        int j = i >> 3, d4 = i & 7;
        *(float4*)&tile[j * 32 + d4 * 4] = *(const float4*)&src[(size_t)j * 512 + d4 * 4];
    }
    __syncthreads();

    int lane = tid & 31, warp = tid >> 5;        // 32 warps, 16 rows each
    int row0 = base + half * 512 + warp * 16;
    const float* tl = tile + lane;
    #pragma unroll 1
    for (int r = 0; r < 16; r++) {
        int row = row0 + r;
        const int2* wj = g_wj + (row * 4 + head) * KEDGE;
        float acc = 0.f;
        #pragma unroll
        for (int k = 0; k < KEDGE; k++) {
            int2 p = wj[k];                       // warp-uniform LDG.64, L1 broadcast
            acc += __int_as_float(p.x) * tl[p.y];
        }
        float o = acc > 0.f ? acc : expm1f(acc);
        g_xc[(size_t)row * 512 + head * 128 + dc * 32 + lane] = o;
    }
}

// ---------------- K4: h2 = xc @ W_out, fused f1o/f2o ----------------
__global__ void k_gemm2(const float* __restrict__ W, const float* __restrict__ a_out) {
    __shared__ float Xs[32][132];
    __shared__ float Wsm[128][33];
    int r0 = blockIdx.x * 32;
    int tid = threadIdx.x;
    int lane = tid & 31, wid = tid >> 5;

    float acc[4] = {0.f, 0.f, 0.f, 0.f};
    for (int kc = 0; kc < 512; kc += 128) {
        #pragma unroll
        for (int t = 0; t < 16; t++) {
            int e = t * 256 + tid;
            { int r = e >> 7, k = e & 127;
              Xs[r][k] = g_xc[(size_t)(r0 + r) * 512 + kc + k]; }
            { int k = e >> 5, n = e & 31;
              Wsm[k][n] = W[(kc + k) * 32 + n]; }
        }
        __syncthreads();
        #pragma unroll 8
        for (int kk = 0; kk < 128; kk++) {
            float w = Wsm[kk][lane];
            #pragma unroll
            for (int r = 0; r < 4; r++) acc[r] += Xs[wid * 4 + r][kk] * w;
        }
        __syncthreads();
    }
    float a1 = a_out[lane];
    float a2 = a_out[32 + lane];
    #pragma unroll
    for (int r = 0; r < 4; r++) {
        int row = r0 + wid * 4 + r;
        g_h2[row * 32 + lane] = acc[r];
        float s1 = acc[r] * a1;
        float s2 = acc[r] * a2;
        #pragma unroll
        for (int o = 16; o; o >>= 1) {
            s1 += __shfl_xor_sync(0xffffffffu, s1, o);
            s2 += __shfl_xor_sync(0xffffffffu, s2, o);
        }
        if (lane == 0) { g_f1o[row] = s1; g_f2o[row] = s2; }
    }
}

// ---------------- K5: layer-2 attention + elu + log_softmax ----------------
__global__ void k_attn2(const int* __restrict__ edge, float* __restrict__ out) {
    int row  = blockIdx.x * 4 + (threadIdx.x >> 5);
    int lane = threadIdx.x & 31;
    int base = row & ~1023;

    int e = edge[row * KEDGE + lane];
    bool valid = (e >= 0);
    unsigned key = valid ? (unsigned)e : (0x40000000u + (unsigned)lane);
    unsigned grp = __match_any_sync(0xffffffffu, key);
    bool uniq = valid && ((__ffs(grp) - 1) == lane);

    float p = 0.f;
    if (uniq) {
        float t = g_f1o[row] + g_f2o[base + e];
        float la = (t > 0.f) ? t : ALPHA_LRELU * t;
        p = __expf(la);
    }
    float s = p;
    #pragma unroll
    for (int o = 16; o; o >>= 1) s += __shfl_xor_sync(0xffffffffu, s, o);
    float wgt = p / s;
    int j = valid ? e : 0;

    float acc = 0.f;
    #pragma unroll 8
    for (int k = 0; k < KEDGE; k++) {
        float wk = __shfl_sync(0xffffffffu, wgt, k);
        int   jk = __shfl_sync(0xffffffffu, j, k);
        acc += wk * g_h2[(base + jk) * 32 + lane];
    }
    float v = acc > 0.f ? acc : expm1f(acc);
    float m2 = v;
    #pragma unroll
    for (int o = 16; o; o >>= 1) m2 = fmaxf(m2, __shfl_xor_sync(0xffffffffu, m2, o));
    float se = __expf(v - m2);
    #pragma unroll
    for (int o = 16; o; o >>= 1) se += __shfl_xor_sync(0xffffffffu, se, o);
    out[row * 32 + lane] = v - m2 - logf(se);
}

// ---------------- launch ----------------
extern "C" void kernel_launch(void* const* d_in, const int* in_sizes, int n_in,
                              void* d_out, int out_size) {
    const float* x     = (const float*)d_in[0];
    const int*   edge  = (const int*)d_in[1];
    const float* Ws    = (const float*)d_in[3];
    const float* a     = (const float*)d_in[4];
    const float* W_out = (const float*)d_in[5];
    const float* a_out = (const float*)d_in[6];
    float* out = (float*)d_out;

    static bool attr_set = false;
    if (!attr_set) {
        cudaFuncSetAttribute(k_attn1_agg, cudaFuncAttributeMaxDynamicSharedMemorySize,
                             1024 * 32 * sizeof(float));
        attr_set = true;
    }

    dim3 g1(4, 32);
    k_gemm1<<<g1, 256>>>(x, Ws, a);
    k_wgt<<<N_NODES / 4, 512>>>(edge);
    dim3 ga(4, 4, 8);
    k_attn1_agg<<<ga, 1024, 1024 * 32 * sizeof(float)>>>();
    k_gemm2<<<N_NODES / 32, 256>>>(W_out, a_out);
    k_attn2<<<N_NODES / 4, 128>>>(edge, out);
}